// round 4
// baseline (speedup 1.0000x reference)
#include <cuda_runtime.h>
#include <math.h>

#define N_NODES 100000
#define N_EDGES 1600000
#define NF 512
#define NH 128
#define NC 40

// ---------------- scratch (static device globals; no allocation) ----------------
__device__ __align__(16) float g_deg [N_NODES];
__device__ __align__(16) float g_dinv[N_NODES];
__device__ __align__(16) float g_hs1 [(size_t)N_NODES * NH];   // h1 * dinv[row]
__device__ __align__(16) float g_agg1[(size_t)N_NODES * NH];   // edge-aggregated hs1
__device__ __align__(16) float g_hs2 [(size_t)N_NODES * NC];   // h2 * dinv[row]
__device__ __align__(16) float g_agg2[(size_t)N_NODES * NC];   // edge-aggregated hs2

// ---------------- helpers ----------------
__device__ __forceinline__ unsigned long long dup2(float a) {
    unsigned int u = __float_as_uint(a);
    unsigned long long r;
    asm("mov.b64 %0, {%1, %2};" : "=l"(r) : "r"(u), "r"(u));
    return r;
}
__device__ __forceinline__ void fma2(unsigned long long& d,
                                     unsigned long long a,
                                     unsigned long long b) {
    // packed f32x2 FMA (Blackwell): 2x fp32 throughput vs scalar FFMA
    asm("fma.rn.f32x2 %0, %1, %2, %0;" : "+l"(d) : "l"(a), "l"(b));
}
__device__ __forceinline__ void red_add_v4(float* p, float4 v) {
    asm volatile("red.global.add.v4.f32 [%0], {%1, %2, %3, %4};"
                 :: "l"(p), "f"(v.x), "f"(v.y), "f"(v.z), "f"(v.w)
                 : "memory");
}

// ---------------- degree / dinv ----------------
__global__ void k_zero_deg() {
    int i = blockIdx.x * blockDim.x + threadIdx.x;
    if (i < N_NODES) g_deg[i] = 0.0f;
}
__global__ void k_deg(const int* __restrict__ ei) {
    int e = blockIdx.x * blockDim.x + threadIdx.x;
    if (e < N_EDGES) {
        int d = ei[N_EDGES + e];
        atomicAdd(&g_deg[d], 1.0f);
    }
}
__global__ void k_dinv() {
    int i = blockIdx.x * blockDim.x + threadIdx.x;
    if (i < N_NODES) g_dinv[i] = rsqrtf(g_deg[i] + 1.0f);   // +1 = self loop
}

// ---------------- GEMM1: hs1 = (x @ W1) * dinv[row]; agg1 = 0 ----------------
// BM=128, BN=128(=NH), BK=16, 256 threads, 8x8 per thread via packed f32x2
#define BM 128
#define BK 16
__global__ void __launch_bounds__(256, 2)
k_gemm1(const float* __restrict__ X, const float* __restrict__ W1) {
    __shared__ float As[BK][BM];        // transposed A tile
    __shared__ float Bs[BK][NH];

    const int tid = threadIdx.x;
    const int tx = tid & 15;            // 16 cols of threads (8 outs each)
    const int ty = tid >> 4;            // 16 rows of threads (8 outs each)
    const int block_row = blockIdx.x * BM;

    unsigned long long acc[8][4];
    #pragma unroll
    for (int i = 0; i < 8; i++)
        #pragma unroll
        for (int j = 0; j < 4; j++) acc[i][j] = 0ull;

    for (int k0 = 0; k0 < NF; k0 += BK) {
        // load A tile: 128x16 floats = 512 float4, 2 per thread
        #pragma unroll
        for (int i = 0; i < 2; i++) {
            int idx = tid + i * 256;            // 0..511
            int r   = idx >> 2;                 // 4 float4 per row
            int c4  = (idx & 3) * 4;
            int grow = block_row + r;
            float4 v = make_float4(0.f, 0.f, 0.f, 0.f);
            if (grow < N_NODES)
                v = *(const float4*)(X + (size_t)grow * NF + k0 + c4);
            As[c4 + 0][r] = v.x; As[c4 + 1][r] = v.y;
            As[c4 + 2][r] = v.z; As[c4 + 3][r] = v.w;
        }
        // load B tile: 16x128 floats = 512 float4, 2 per thread
        #pragma unroll
        for (int i = 0; i < 2; i++) {
            int idx = tid + i * 256;
            int r   = idx >> 5;                 // 32 float4 per row
            int c4  = (idx & 31) * 4;
            *(float4*)&Bs[r][c4] = *(const float4*)(W1 + (size_t)(k0 + r) * NH + c4);
        }
        __syncthreads();

        #pragma unroll
        for (int k = 0; k < BK; k++) {
            float4 a0 = *(float4*)&As[k][ty * 8];
            float4 a1 = *(float4*)&As[k][ty * 8 + 4];
            ulonglong2 q0 = *(ulonglong2*)&Bs[k][tx * 8];
            ulonglong2 q1 = *(ulonglong2*)&Bs[k][tx * 8 + 4];
            unsigned long long bb[4] = {q0.x, q0.y, q1.x, q1.y};
            float av[8] = {a0.x, a0.y, a0.z, a0.w, a1.x, a1.y, a1.z, a1.w};
            #pragma unroll
            for (int i = 0; i < 8; i++) {
                unsigned long long aa = dup2(av[i]);
                #pragma unroll
                for (int j = 0; j < 4; j++) fma2(acc[i][j], aa, bb[j]);
            }
        }
        __syncthreads();
    }

    // epilogue: scale by dinv, write hs1, zero agg1
    #pragma unroll
    for (int i = 0; i < 8; i++) {
        int row = block_row + ty * 8 + i;
        if (row < N_NODES) {
            float dv = g_dinv[row];
            #pragma unroll
            for (int jh = 0; jh < 2; jh++) {
                float2 p0 = *(float2*)&acc[i][jh * 2 + 0];
                float2 p1 = *(float2*)&acc[i][jh * 2 + 1];
                float4 v = make_float4(p0.x * dv, p0.y * dv, p1.x * dv, p1.y * dv);
                size_t off = (size_t)row * NH + tx * 8 + jh * 4;
                *(float4*)(g_hs1 + off)  = v;
                *(float4*)(g_agg1 + off) = make_float4(0.f, 0.f, 0.f, 0.f);
            }
        }
    }
}

// ---------------- edge scatter, layer 1 (128 floats/edge, warp/edge) ----------------
__global__ void k_scatter1(const int* __restrict__ ei) {
    int gw   = blockIdx.x * 8 + (threadIdx.x >> 5);
    int lane = threadIdx.x & 31;
    if (gw >= N_EDGES) return;
    int s = 0, d = 0;
    if (lane == 0) { s = ei[gw]; d = ei[N_EDGES + gw]; }
    s = __shfl_sync(0xffffffffu, s, 0);
    d = __shfl_sync(0xffffffffu, d, 0);
    float4 v = *(const float4*)(g_hs1 + (size_t)s * NH + lane * 4);
    red_add_v4(g_agg1 + (size_t)d * NH + lane * 4, v);
}

// ---- fused: z = relu(dinv*(agg1+hs1)+b1); hs2 = dinv*(z@W2); agg2 = 0 ----
// block = 256 threads, 32 rows per block
__global__ void __launch_bounds__(256)
k_hs2(const float* __restrict__ b1, const float* __restrict__ W2) {
    __shared__ float W2s[NH * NC];      // 20 KB
    __shared__ float zs[32][NH + 1];    // padded vs bank conflicts
    __shared__ float b1s[NH];
    __shared__ float dvs[32];

    const int tid = threadIdx.x;
    const int r0  = blockIdx.x * 32;

    #pragma unroll
    for (int i = 0; i < (NH * NC + 255) / 256; i++) {
        int idx = tid + i * 256;
        if (idx < NH * NC) W2s[idx] = W2[idx];
    }
    if (tid < NH) b1s[tid] = b1[tid];
    if (tid < 32) dvs[tid] = g_dinv[r0 + tid];
    __syncthreads();

    // phase A: compute z rows into smem
    #pragma unroll
    for (int i = 0; i < 16; i++) {
        int e = tid + i * 256;          // 0..4095
        int r = e >> 7;
        int c = e & (NH - 1);
        size_t off = (size_t)(r0 + r) * NH + c;
        float v = dvs[r] * (g_agg1[off] + g_hs1[off]) + b1s[c];
        zs[r][c] = fmaxf(v, 0.0f);
    }
    __syncthreads();

    // phase B: 32 rows x 40 cols = 1280 outputs, 5 per thread
    #pragma unroll
    for (int i = 0; i < 5; i++) {
        int o = tid + i * 256;          // 0..1279
        int r = o / NC;
        int c = o - r * NC;
        float acc = 0.0f;
        #pragma unroll 8
        for (int k = 0; k < NH; k++)
            acc = fmaf(zs[r][k], W2s[k * NC + c], acc);
        size_t off = (size_t)(r0 + r) * NC + c;
        g_hs2[off]  = dvs[r] * acc;
        g_agg2[off] = 0.0f;
    }
}

// ---------------- edge scatter, layer 2 (40 floats/edge, 16 lanes/edge) ----------------
__global__ void k_scatter2(const int* __restrict__ ei) {
    int t = blockIdx.x * blockDim.x + threadIdx.x;
    int e = t >> 4;
    int q = t & 15;
    if (e >= N_EDGES) return;
    int lane = threadIdx.x & 31;
    int s = 0, d = 0;
    if ((lane & 15) == 0) { s = ei[e]; d = ei[N_EDGES + e]; }
    s = __shfl_sync(0xffffffffu, s, lane & 16);
    d = __shfl_sync(0xffffffffu, d, lane & 16);
    if (q < 10) {
        float4 v = *(const float4*)(g_hs2 + (size_t)s * NC + q * 4);
        red_add_v4(g_agg2 + (size_t)d * NC + q * 4, v);
    }
}

// ---------------- epilogue: logits + log_softmax, warp per row ----------------
__global__ void k_out(const float* __restrict__ b2, float* __restrict__ out) {
    int row  = blockIdx.x * 8 + (threadIdx.x >> 5);
    int lane = threadIdx.x & 31;
    if (row >= N_NODES) return;
    float dv = g_dinv[row];
    size_t base = (size_t)row * NC;

    float v0 = dv * (g_agg2[base + lane] + g_hs2[base + lane]) + b2[lane];
    float v1 = -3.0e38f;
    if (lane < 8)
        v1 = dv * (g_agg2[base + 32 + lane] + g_hs2[base + 32 + lane]) + b2[32 + lane];

    float m = fmaxf(v0, v1);
    #pragma unroll
    for (int off = 16; off; off >>= 1)
        m = fmaxf(m, __shfl_xor_sync(0xffffffffu, m, off));

    float ssum = expf(v0 - m) + ((lane < 8) ? expf(v1 - m) : 0.0f);
    #pragma unroll
    for (int off = 16; off; off >>= 1)
        ssum += __shfl_xor_sync(0xffffffffu, ssum, off);

    float lse = m + logf(ssum);
    out[base + lane] = v0 - lse;
    if (lane < 8) out[base + 32 + lane] = v1 - lse;
}

// ---------------- launch ----------------
extern "C" void kernel_launch(void* const* d_in, const int* in_sizes, int n_in,
                              void* d_out, int out_size) {
    // Bind inputs by element count (robust to metadata ordering):
    //   x  = 100000*512 = 51200000   ei = 2*1600000 = 3200000 (int32!)
    //   W1 = 512*128    = 65536      b1 = 128
    //   W2 = 128*40     = 5120       b2 = 40
    const float* x = 0; const int* ei = 0;
    const float* W1 = 0; const float* b1 = 0;
    const float* W2 = 0; const float* b2 = 0;
    for (int i = 0; i < n_in; i++) {
        switch (in_sizes[i]) {
            case 51200000: x  = (const float*)d_in[i]; break;
            case 3200000:  ei = (const int*)d_in[i];   break;
            case 65536:    W1 = (const float*)d_in[i]; break;
            case 128:      b1 = (const float*)d_in[i]; break;
            case 5120:     W2 = (const float*)d_in[i]; break;
            case 40:       b2 = (const float*)d_in[i]; break;
        }
    }
    float* out = (float*)d_out;

    k_zero_deg<<<(N_NODES + 255) / 256, 256>>>();
    k_deg<<<(N_EDGES + 255) / 256, 256>>>(ei);
    k_dinv<<<(N_NODES + 255) / 256, 256>>>();

    k_gemm1<<<(N_NODES + BM - 1) / BM, 256>>>(x, W1);        // 782 blocks
    k_scatter1<<<N_EDGES / 8, 256>>>(ei);                    // warp per edge

    k_hs2<<<N_NODES / 32, 256>>>(b1, W2);                    // 3125 blocks
    k_scatter2<<<(N_EDGES * 16) / 256, 256>>>(ei);           // 16 lanes per edge

    k_out<<<N_NODES / 8, 256>>>(b2, out);                    // warp per row
}

// round 5
// speedup vs baseline: 1.3018x; 1.3018x over previous
#include <cuda_runtime.h>
#include <math.h>

#define N_NODES 100000
#define N_EDGES 1600000
#define NF 512
#define NH 128
#define NC 40

// ---------------- scratch (static device globals; no allocation) ----------------
__device__ __align__(16) float g_deg [N_NODES];
__device__ __align__(16) float g_dinv[N_NODES];
__device__ __align__(16) float g_hs1 [(size_t)N_NODES * NH];   // h1 * dinv[row]
__device__ __align__(16) float g_agg1[(size_t)N_NODES * NH];   // edge-aggregated hs1
__device__ __align__(16) float g_hs2 [(size_t)N_NODES * NC];   // h2 * dinv[row]
__device__ __align__(16) float g_agg2[(size_t)N_NODES * NC];   // edge-aggregated hs2

// ---------------- helpers ----------------
__device__ __forceinline__ void red_add_v4(float* p, float4 v) {
    asm volatile("red.global.add.v4.f32 [%0], {%1, %2, %3, %4};"
                 :: "l"(p), "f"(v.x), "f"(v.y), "f"(v.z), "f"(v.w)
                 : "memory");
}
__device__ __forceinline__ unsigned int f2tf32(float f) {
    unsigned int r;
    asm("cvt.rna.tf32.f32 %0, %1;" : "=r"(r) : "f"(f));
    return r;
}
__device__ __forceinline__ void mma_tf32(float* c, const unsigned int* a, const unsigned int* b) {
    asm("mma.sync.aligned.m16n8k8.row.col.f32.tf32.tf32.f32 "
        "{%0,%1,%2,%3}, {%4,%5,%6,%7}, {%8,%9}, {%0,%1,%2,%3};"
        : "+f"(c[0]), "+f"(c[1]), "+f"(c[2]), "+f"(c[3])
        : "r"(a[0]), "r"(a[1]), "r"(a[2]), "r"(a[3]), "r"(b[0]), "r"(b[1]));
}

// ---------------- degree / dinv ----------------
__global__ void k_zero_deg() {
    int i = blockIdx.x * blockDim.x + threadIdx.x;
    if (i < N_NODES) g_deg[i] = 0.0f;
}
__global__ void k_deg(const int* __restrict__ ei) {
    int e = blockIdx.x * blockDim.x + threadIdx.x;
    if (e < N_EDGES) {
        int d = ei[N_EDGES + e];
        atomicAdd(&g_deg[d], 1.0f);
    }
}
__global__ void k_dinv() {
    int i = blockIdx.x * blockDim.x + threadIdx.x;
    if (i < N_NODES) g_dinv[i] = rsqrtf(g_deg[i] + 1.0f);   // +1 = self loop
}

// ---------------- GEMM1 (tf32 tensor cores): hs1 = (x@W1)*dinv; agg1 = 0 ----
// BM=128, BN=128(=NH), BK=32, 256 threads = 8 warps (2x4 warp grid),
// warp tile 64x32 via m16n8k8: 4 m-tiles x 4 n-tiles.
#define BM 128
#define BK 32
#define AS_STR 36   // (4r+c)&31 unique across a warp's fragment load
#define BS_STR 132  // (4k+n)&31 unique across a warp's fragment load
__global__ void __launch_bounds__(256, 2)
k_gemm1(const float* __restrict__ X, const float* __restrict__ W1) {
    __shared__ unsigned int As[BM][AS_STR];   // tf32 bits, [row][k]
    __shared__ unsigned int Bs[BK][BS_STR];   // tf32 bits, [k][col]

    const int tid    = threadIdx.x;
    const int lane   = tid & 31;
    const int wid    = tid >> 5;
    const int warp_m = wid >> 2;              // 0..1  -> 64 rows each
    const int warp_n = wid & 3;               // 0..3  -> 32 cols each
    const int block_row = blockIdx.x * BM;

    const int grp = lane >> 2;                // 0..7
    const int qid = lane & 3;                 // 0..3

    float acc[4][4][4];                       // [mt][nt][frag]
    #pragma unroll
    for (int i = 0; i < 4; i++)
        #pragma unroll
        for (int j = 0; j < 4; j++)
            #pragma unroll
            for (int q = 0; q < 4; q++) acc[i][j][q] = 0.0f;

    for (int k0 = 0; k0 < NF; k0 += BK) {
        // stage A: 128x32 f32 -> tf32 smem. 1024 float4, 4 per thread.
        #pragma unroll
        for (int i = 0; i < 4; i++) {
            int idx = tid + i * 256;          // 0..1023
            int r   = idx >> 3;               // 8 float4 per row
            int c4  = (idx & 7) * 4;
            int grow = block_row + r;
            float4 v = make_float4(0.f, 0.f, 0.f, 0.f);
            if (grow < N_NODES)
                v = *(const float4*)(X + (size_t)grow * NF + k0 + c4);
            As[r][c4 + 0] = f2tf32(v.x);
            As[r][c4 + 1] = f2tf32(v.y);
            As[r][c4 + 2] = f2tf32(v.z);
            As[r][c4 + 3] = f2tf32(v.w);
        }
        // stage B: 32x128 f32 -> tf32 smem. 1024 float4, 4 per thread.
        #pragma unroll
        for (int i = 0; i < 4; i++) {
            int idx = tid + i * 256;
            int r   = idx >> 5;               // 32 float4 per row
            int c4  = (idx & 31) * 4;
            float4 v = *(const float4*)(W1 + (size_t)(k0 + r) * NH + c4);
            Bs[r][c4 + 0] = f2tf32(v.x);
            Bs[r][c4 + 1] = f2tf32(v.y);
            Bs[r][c4 + 2] = f2tf32(v.z);
            Bs[r][c4 + 3] = f2tf32(v.w);
        }
        __syncthreads();

        #pragma unroll
        for (int kk = 0; kk < BK; kk += 8) {
            // A fragments: 4 m-tiles
            unsigned int af[4][4];
            #pragma unroll
            for (int mt = 0; mt < 4; mt++) {
                int r = warp_m * 64 + mt * 16;
                af[mt][0] = As[r + grp    ][kk + qid    ];
                af[mt][1] = As[r + grp + 8][kk + qid    ];
                af[mt][2] = As[r + grp    ][kk + qid + 4];
                af[mt][3] = As[r + grp + 8][kk + qid + 4];
            }
            // B fragments: 4 n-tiles
            unsigned int bf[4][2];
            #pragma unroll
            for (int nt = 0; nt < 4; nt++) {
                int c = warp_n * 32 + nt * 8 + grp;
                bf[nt][0] = Bs[kk + qid    ][c];
                bf[nt][1] = Bs[kk + qid + 4][c];
            }
            #pragma unroll
            for (int mt = 0; mt < 4; mt++)
                #pragma unroll
                for (int nt = 0; nt < 4; nt++)
                    mma_tf32(acc[mt][nt], af[mt], bf[nt]);
        }
        __syncthreads();
    }

    // epilogue: scale by dinv, write hs1, zero agg1
    #pragma unroll
    for (int mt = 0; mt < 4; mt++) {
        int r1 = block_row + warp_m * 64 + mt * 16 + grp;
        int r2 = r1 + 8;
        float dv1 = (r1 < N_NODES) ? g_dinv[r1] : 0.0f;
        float dv2 = (r2 < N_NODES) ? g_dinv[r2] : 0.0f;
        #pragma unroll
        for (int nt = 0; nt < 4; nt++) {
            int col = warp_n * 32 + nt * 8 + qid * 2;
            if (r1 < N_NODES) {
                size_t o1 = (size_t)r1 * NH + col;
                *(float2*)(g_hs1 + o1)  = make_float2(acc[mt][nt][0] * dv1, acc[mt][nt][1] * dv1);
                *(float2*)(g_agg1 + o1) = make_float2(0.f, 0.f);
            }
            if (r2 < N_NODES) {
                size_t o2 = (size_t)r2 * NH + col;
                *(float2*)(g_hs1 + o2)  = make_float2(acc[mt][nt][2] * dv2, acc[mt][nt][3] * dv2);
                *(float2*)(g_agg2 + 0) = *(float2*)(g_agg2 + 0); // no-op placeholder removed below
                *(float2*)(g_agg1 + o2) = make_float2(0.f, 0.f);
            }
        }
    }
}

// ---------------- edge scatter, layer 1 (128 floats/edge, warp/edge) ----------------
__global__ void k_scatter1(const int* __restrict__ ei) {
    int gw   = blockIdx.x * 8 + (threadIdx.x >> 5);
    int lane = threadIdx.x & 31;
    if (gw >= N_EDGES) return;
    int s = 0, d = 0;
    if (lane == 0) { s = ei[gw]; d = ei[N_EDGES + gw]; }
    s = __shfl_sync(0xffffffffu, s, 0);
    d = __shfl_sync(0xffffffffu, d, 0);
    float4 v = *(const float4*)(g_hs1 + (size_t)s * NH + lane * 4);
    red_add_v4(g_agg1 + (size_t)d * NH + lane * 4, v);
}

// ---- fused: z = relu(dinv*(agg1+hs1)+b1); hs2 = dinv*(z@W2); agg2 = 0 ----
__global__ void __launch_bounds__(256)
k_hs2(const float* __restrict__ b1, const float* __restrict__ W2) {
    __shared__ float W2s[NH * NC];      // 20 KB
    __shared__ float zs[32][NH + 1];    // padded vs bank conflicts
    __shared__ float b1s[NH];
    __shared__ float dvs[32];

    const int tid = threadIdx.x;
    const int r0  = blockIdx.x * 32;

    #pragma unroll
    for (int i = 0; i < (NH * NC + 255) / 256; i++) {
        int idx = tid + i * 256;
        if (idx < NH * NC) W2s[idx] = W2[idx];
    }
    if (tid < NH) b1s[tid] = b1[tid];
    if (tid < 32) dvs[tid] = g_dinv[r0 + tid];
    __syncthreads();

    #pragma unroll
    for (int i = 0; i < 16; i++) {
        int e = tid + i * 256;          // 0..4095
        int r = e >> 7;
        int c = e & (NH - 1);
        size_t off = (size_t)(r0 + r) * NH + c;
        float v = dvs[r] * (g_agg1[off] + g_hs1[off]) + b1s[c];
        zs[r][c] = fmaxf(v, 0.0f);
    }
    __syncthreads();

    #pragma unroll
    for (int i = 0; i < 5; i++) {
        int o = tid + i * 256;          // 0..1279
        int r = o / NC;
        int c = o - r * NC;
        float acc = 0.0f;
        #pragma unroll 8
        for (int k = 0; k < NH; k++)
            acc = fmaf(zs[r][k], W2s[k * NC + c], acc);
        size_t off = (size_t)(r0 + r) * NC + c;
        g_hs2[off]  = dvs[r] * acc;
        g_agg2[off] = 0.0f;
    }
}

// ---------------- edge scatter, layer 2 (40 floats/edge, 16 lanes/edge) ----------------
__global__ void k_scatter2(const int* __restrict__ ei) {
    int t = blockIdx.x * blockDim.x + threadIdx.x;
    int e = t >> 4;
    int q = t & 15;
    if (e >= N_EDGES) return;
    int lane = threadIdx.x & 31;
    int s = 0, d = 0;
    if ((lane & 15) == 0) { s = ei[e]; d = ei[N_EDGES + e]; }
    s = __shfl_sync(0xffffffffu, s, lane & 16);
    d = __shfl_sync(0xffffffffu, d, lane & 16);
    if (q < 10) {
        float4 v = *(const float4*)(g_hs2 + (size_t)s * NC + q * 4);
        red_add_v4(g_agg2 + (size_t)d * NC + q * 4, v);
    }
}

// ---------------- epilogue: logits + log_softmax, warp per row ----------------
__global__ void k_out(const float* __restrict__ b2, float* __restrict__ out) {
    int row  = blockIdx.x * 8 + (threadIdx.x >> 5);
    int lane = threadIdx.x & 31;
    if (row >= N_NODES) return;
    float dv = g_dinv[row];
    size_t base = (size_t)row * NC;

    float v0 = dv * (g_agg2[base + lane] + g_hs2[base + lane]) + b2[lane];
    float v1 = -3.0e38f;
    if (lane < 8)
        v1 = dv * (g_agg2[base + 32 + lane] + g_hs2[base + 32 + lane]) + b2[32 + lane];

    float m = fmaxf(v0, v1);
    #pragma unroll
    for (int off = 16; off; off >>= 1)
        m = fmaxf(m, __shfl_xor_sync(0xffffffffu, m, off));

    float ssum = expf(v0 - m) + ((lane < 8) ? expf(v1 - m) : 0.0f);
    #pragma unroll
    for (int off = 16; off; off >>= 1)
        ssum += __shfl_xor_sync(0xffffffffu, ssum, off);

    float lse = m + logf(ssum);
    out[base + lane] = v0 - lse;
    if (lane < 8) out[base + 32 + lane] = v1 - lse;
}

// ---------------- launch ----------------
extern "C" void kernel_launch(void* const* d_in, const int* in_sizes, int n_in,
                              void* d_out, int out_size) {
    const float* x = 0; const int* ei = 0;
    const float* W1 = 0; const float* b1 = 0;
    const float* W2 = 0; const float* b2 = 0;
    for (int i = 0; i < n_in; i++) {
        switch (in_sizes[i]) {
            case 51200000: x  = (const float*)d_in[i]; break;
            case 3200000:  ei = (const int*)d_in[i];   break;
            case 65536:    W1 = (const float*)d_in[i]; break;
            case 128:      b1 = (const float*)d_in[i]; break;
            case 5120:     W2 = (const float*)d_in[i]; break;
            case 40:       b2 = (const float*)d_in[i]; break;
        }
    }
    float* out = (float*)d_out;

    k_zero_deg<<<(N_NODES + 255) / 256, 256>>>();
    k_deg<<<(N_EDGES + 255) / 256, 256>>>(ei);
    k_dinv<<<(N_NODES + 255) / 256, 256>>>();

    k_gemm1<<<(N_NODES + BM - 1) / BM, 256>>>(x, W1);        // 782 blocks, tf32 MMA
    k_scatter1<<<N_EDGES / 8, 256>>>(ei);                    // warp per edge

    k_hs2<<<N_NODES / 32, 256>>>(b1, W2);                    // 3125 blocks
    k_scatter2<<<(N_EDGES * 16) / 256, 256>>>(ei);           // 16 lanes per edge

    k_out<<<N_NODES / 8, 256>>>(b2, out);                    // warp per row
}

// round 6
// speedup vs baseline: 1.5329x; 1.1776x over previous
#include <cuda_runtime.h>
#include <math.h>

#define N_NODES 100000
#define N_EDGES 1600000
#define NF 512
#define NH 128
#define NC 40

// ---------------- scratch (static device globals; no allocation) ----------------
__device__ __align__(16) int   g_cnt   [N_NODES];
__device__ __align__(16) int   g_rowptr[N_NODES + 1];
__device__ __align__(16) int   g_cursor[N_NODES];
__device__ __align__(16) int   g_csr   [N_EDGES];
__device__ __align__(16) float g_dinv  [N_NODES];
__device__ __align__(16) float g_hs1   [(size_t)N_NODES * NH];  // (x@W1) * dinv[row]
__device__ __align__(16) float g_hs2   [(size_t)N_NODES * NC];  // dinv*(z@W2)

// ---------------- helpers ----------------
__device__ __forceinline__ unsigned int f2tf32(float f) {
    unsigned int r;
    asm("cvt.rna.tf32.f32 %0, %1;" : "=r"(r) : "f"(f));
    return r;
}
__device__ __forceinline__ void mma_tf32(float* c, const unsigned int* a, const unsigned int* b) {
    asm("mma.sync.aligned.m16n8k8.row.col.f32.tf32.tf32.f32 "
        "{%0,%1,%2,%3}, {%4,%5,%6,%7}, {%8,%9}, {%0,%1,%2,%3};"
        : "+f"(c[0]), "+f"(c[1]), "+f"(c[2]), "+f"(c[3])
        : "r"(a[0]), "r"(a[1]), "r"(a[2]), "r"(a[3]), "r"(b[0]), "r"(b[1]));
}

// ---------------- degree / dinv / CSR ----------------
__global__ void k_zero_cnt() {
    int i = blockIdx.x * blockDim.x + threadIdx.x;
    if (i < N_NODES) g_cnt[i] = 0;
}
__global__ void k_deg(const int* __restrict__ ei) {
    int e = blockIdx.x * blockDim.x + threadIdx.x;
    if (e < N_EDGES) atomicAdd(&g_cnt[ei[N_EDGES + e]], 1);
}
__global__ void k_dinv() {
    int i = blockIdx.x * blockDim.x + threadIdx.x;
    if (i < N_NODES) g_dinv[i] = rsqrtf((float)g_cnt[i] + 1.0f);  // +1 self loop
}
// single-block exclusive scan of g_cnt -> g_rowptr, g_cursor
__global__ void __launch_bounds__(1024) k_scan() {
    __shared__ int sums[1024];
    const int t  = threadIdx.x;
    const int CH = (N_NODES + 1023) / 1024;    // 98
    int start = t * CH;
    int end   = start + CH; if (end > N_NODES) end = N_NODES;
    int s = 0;
    for (int i = start; i < end; i++) s += g_cnt[i];
    sums[t] = s;
    __syncthreads();
    for (int off = 1; off < 1024; off <<= 1) {
        int add = (t >= off) ? sums[t - off] : 0;
        __syncthreads();
        sums[t] += add;
        __syncthreads();
    }
    int run = (t == 0) ? 0 : sums[t - 1];
    for (int i = start; i < end; i++) {
        g_rowptr[i] = run;
        g_cursor[i] = run;
        run += g_cnt[i];
    }
    if (t == 0) g_rowptr[N_NODES] = sums[1023];
}
__global__ void k_fill(const int* __restrict__ ei) {
    int e = blockIdx.x * blockDim.x + threadIdx.x;
    if (e < N_EDGES) {
        int s = ei[e], d = ei[N_EDGES + e];
        int pos = atomicAdd(&g_cursor[d], 1);
        g_csr[pos] = s;
    }
}

// ---------------- GEMM1 (tf32 tensor cores): hs1 = (x@W1)*dinv ----------------
#define BM 128
#define BK 32
#define AS_STR 36
#define BS_STR 132
__global__ void __launch_bounds__(256, 2)
k_gemm1(const float* __restrict__ X, const float* __restrict__ W1) {
    __shared__ unsigned int As[BM][AS_STR];   // tf32 bits, [row][k]
    __shared__ unsigned int Bs[BK][BS_STR];   // tf32 bits, [k][col]

    const int tid    = threadIdx.x;
    const int lane   = tid & 31;
    const int wid    = tid >> 5;
    const int warp_m = wid >> 2;
    const int warp_n = wid & 3;
    const int block_row = blockIdx.x * BM;

    const int grp = lane >> 2;
    const int qid = lane & 3;

    float acc[4][4][4];
    #pragma unroll
    for (int i = 0; i < 4; i++)
        #pragma unroll
        for (int j = 0; j < 4; j++)
            #pragma unroll
            for (int q = 0; q < 4; q++) acc[i][j][q] = 0.0f;

    for (int k0 = 0; k0 < NF; k0 += BK) {
        #pragma unroll
        for (int i = 0; i < 4; i++) {
            int idx = tid + i * 256;
            int r   = idx >> 3;
            int c4  = (idx & 7) * 4;
            int grow = block_row + r;
            float4 v = make_float4(0.f, 0.f, 0.f, 0.f);
            if (grow < N_NODES)
                v = *(const float4*)(X + (size_t)grow * NF + k0 + c4);
            As[r][c4 + 0] = f2tf32(v.x);
            As[r][c4 + 1] = f2tf32(v.y);
            As[r][c4 + 2] = f2tf32(v.z);
            As[r][c4 + 3] = f2tf32(v.w);
        }
        #pragma unroll
        for (int i = 0; i < 4; i++) {
            int idx = tid + i * 256;
            int r   = idx >> 5;
            int c4  = (idx & 31) * 4;
            float4 v = *(const float4*)(W1 + (size_t)(k0 + r) * NH + c4);
            Bs[r][c4 + 0] = f2tf32(v.x);
            Bs[r][c4 + 1] = f2tf32(v.y);
            Bs[r][c4 + 2] = f2tf32(v.z);
            Bs[r][c4 + 3] = f2tf32(v.w);
        }
        __syncthreads();

        #pragma unroll
        for (int kk = 0; kk < BK; kk += 8) {
            unsigned int af[4][4];
            #pragma unroll
            for (int mt = 0; mt < 4; mt++) {
                int r = warp_m * 64 + mt * 16;
                af[mt][0] = As[r + grp    ][kk + qid    ];
                af[mt][1] = As[r + grp + 8][kk + qid    ];
                af[mt][2] = As[r + grp    ][kk + qid + 4];
                af[mt][3] = As[r + grp + 8][kk + qid + 4];
            }
            unsigned int bf[4][2];
            #pragma unroll
            for (int nt = 0; nt < 4; nt++) {
                int c = warp_n * 32 + nt * 8 + grp;
                bf[nt][0] = Bs[kk + qid    ][c];
                bf[nt][1] = Bs[kk + qid + 4][c];
            }
            #pragma unroll
            for (int mt = 0; mt < 4; mt++)
                #pragma unroll
                for (int nt = 0; nt < 4; nt++)
                    mma_tf32(acc[mt][nt], af[mt], bf[nt]);
        }
        __syncthreads();
    }

    #pragma unroll
    for (int mt = 0; mt < 4; mt++) {
        int r1 = block_row + warp_m * 64 + mt * 16 + grp;
        int r2 = r1 + 8;
        float dv1 = (r1 < N_NODES) ? g_dinv[r1] : 0.0f;
        float dv2 = (r2 < N_NODES) ? g_dinv[r2] : 0.0f;
        #pragma unroll
        for (int nt = 0; nt < 4; nt++) {
            int col = warp_n * 32 + nt * 8 + qid * 2;
            if (r1 < N_NODES)
                *(float2*)(g_hs1 + (size_t)r1 * NH + col) =
                    make_float2(acc[mt][nt][0] * dv1, acc[mt][nt][1] * dv1);
            if (r2 < N_NODES)
                *(float2*)(g_hs1 + (size_t)r2 * NH + col) =
                    make_float2(acc[mt][nt][2] * dv2, acc[mt][nt][3] * dv2);
        }
    }
}

// ---- layer1: per node, gather hs1 neighbors + self, relu(dinv*agg+b1), GEMV W2 ----
// 256 threads = 8 warps; 32 nodes per block (each warp does 4 nodes)
__global__ void __launch_bounds__(256)
k_layer1(const float* __restrict__ b1, const float* __restrict__ W2) {
    __shared__ float W2s[NH * NC];    // 20 KB  [k*NC+c]
    __shared__ float zs[8][NH];       // one z row per warp
    __shared__ float b1s[NH];

    const int tid  = threadIdx.x;
    const int warp = tid >> 5;
    const int lane = tid & 31;

    #pragma unroll
    for (int i = 0; i < 20; i++) {
        int idx = tid + i * 256;
        if (idx < NH * NC) W2s[idx] = W2[idx];
    }
    if (tid < NH) b1s[tid] = b1[tid];
    __syncthreads();

    #pragma unroll 1
    for (int it = 0; it < 4; it++) {
        int n = blockIdx.x * 32 + it * 8 + warp;
        // n < N_NODES always (100000 % 32 == 0)
        float dv = g_dinv[n];

        // aggregate: self + neighbors (each lane owns 4 consecutive feats)
        float4 acc = *(const float4*)(g_hs1 + (size_t)n * NH + lane * 4);
        int beg = g_rowptr[n], end = g_rowptr[n + 1];
        int s_next = (beg < end) ? g_csr[beg] : 0;
        for (int e = beg; e < end; e++) {
            int s = s_next;
            if (e + 1 < end) s_next = g_csr[e + 1];
            float4 v = *(const float4*)(g_hs1 + (size_t)s * NH + lane * 4);
            acc.x += v.x; acc.y += v.y; acc.z += v.z; acc.w += v.w;
        }
        // z = relu(dv*acc + b1)
        zs[warp][lane * 4 + 0] = fmaxf(dv * acc.x + b1s[lane * 4 + 0], 0.0f);
        zs[warp][lane * 4 + 1] = fmaxf(dv * acc.y + b1s[lane * 4 + 1], 0.0f);
        zs[warp][lane * 4 + 2] = fmaxf(dv * acc.z + b1s[lane * 4 + 2], 0.0f);
        zs[warp][lane * 4 + 3] = fmaxf(dv * acc.w + b1s[lane * 4 + 3], 0.0f);
        __syncwarp();

        // GEMV: hs2[n] = dv * (z @ W2);  col0 = lane, col1 = 32+lane (lane<8)
        float d0 = 0.0f, d1 = 0.0f;
        #pragma unroll 8
        for (int k = 0; k < NH; k++) {
            float zk = zs[warp][k];
            d0 = fmaf(zk, W2s[k * NC + lane], d0);
            if (lane < 8) d1 = fmaf(zk, W2s[k * NC + 32 + lane], d1);
        }
        g_hs2[(size_t)n * NC + lane] = dv * d0;
        if (lane < 8) g_hs2[(size_t)n * NC + 32 + lane] = dv * d1;
        __syncwarp();
    }
}

// ---- layer2: per node, gather hs2 neighbors + self, bias + log_softmax -> out ----
__global__ void __launch_bounds__(256)
k_layer2(const float* __restrict__ b2, float* __restrict__ out) {
    int n    = blockIdx.x * 8 + (threadIdx.x >> 5);
    int lane = threadIdx.x & 31;
    // n < N_NODES always (100000 % 8 == 0)
    float dv = g_dinv[n];
    size_t base = (size_t)n * NC;

    float v0 = g_hs2[base + lane];
    float v1 = (lane < 8) ? g_hs2[base + 32 + lane] : 0.0f;

    int beg = g_rowptr[n], end = g_rowptr[n + 1];
    int s_next = (beg < end) ? g_csr[beg] : 0;
    for (int e = beg; e < end; e++) {
        int s = s_next;
        if (e + 1 < end) s_next = g_csr[e + 1];
        size_t sb = (size_t)s * NC;
        v0 += g_hs2[sb + lane];
        if (lane < 8) v1 += g_hs2[sb + 32 + lane];
    }

    v0 = dv * v0 + b2[lane];
    v1 = (lane < 8) ? (dv * v1 + b2[32 + lane]) : -3.0e38f;

    float m = fmaxf(v0, v1);
    #pragma unroll
    for (int off = 16; off; off >>= 1)
        m = fmaxf(m, __shfl_xor_sync(0xffffffffu, m, off));

    float ssum = expf(v0 - m) + ((lane < 8) ? expf(v1 - m) : 0.0f);
    #pragma unroll
    for (int off = 16; off; off >>= 1)
        ssum += __shfl_xor_sync(0xffffffffu, ssum, off);

    float lse = m + logf(ssum);
    out[base + lane] = v0 - lse;
    if (lane < 8) out[base + 32 + lane] = v1 - lse;
}

// ---------------- launch ----------------
extern "C" void kernel_launch(void* const* d_in, const int* in_sizes, int n_in,
                              void* d_out, int out_size) {
    const float* x = 0; const int* ei = 0;
    const float* W1 = 0; const float* b1 = 0;
    const float* W2 = 0; const float* b2 = 0;
    for (int i = 0; i < n_in; i++) {
        switch (in_sizes[i]) {
            case 51200000: x  = (const float*)d_in[i]; break;
            case 3200000:  ei = (const int*)d_in[i];   break;
            case 65536:    W1 = (const float*)d_in[i]; break;
            case 128:      b1 = (const float*)d_in[i]; break;
            case 5120:     W2 = (const float*)d_in[i]; break;
            case 40:       b2 = (const float*)d_in[i]; break;
        }
    }
    float* out = (float*)d_out;

    k_zero_cnt<<<(N_NODES + 255) / 256, 256>>>();
    k_deg<<<(N_EDGES + 255) / 256, 256>>>(ei);
    k_dinv<<<(N_NODES + 255) / 256, 256>>>();
    k_scan<<<1, 1024>>>();
    k_fill<<<(N_EDGES + 255) / 256, 256>>>(ei);

    k_gemm1<<<(N_NODES + BM - 1) / BM, 256>>>(x, W1);   // 782 blocks, tf32 MMA
    k_layer1<<<N_NODES / 32, 256>>>(b1, W2);            // 3125 blocks
    k_layer2<<<N_NODES / 8, 256>>>(b2, out);            // 12500 blocks
}

// round 7
// speedup vs baseline: 2.1375x; 1.3944x over previous
#include <cuda_runtime.h>
#include <math.h>

#define N_NODES 100000
#define N_EDGES 1600000
#define NF 512
#define NH 128
#define NC 40

#define SCAN_CH  128
#define SCAN_NB  ((N_NODES + SCAN_CH - 1) / SCAN_CH)   // 782

// ---------------- scratch (static device globals; no allocation) ----------------
__device__ __align__(16) int   g_cnt   [N_NODES];
__device__ __align__(16) int   g_rowptr[N_NODES + 1];
__device__ __align__(16) int   g_cursor[N_NODES];
__device__ __align__(16) int   g_csr   [N_EDGES];
__device__ __align__(16) int   g_bsum  [SCAN_NB];
__device__ __align__(16) int   g_boff  [SCAN_NB];
__device__ __align__(16) float g_dinv  [N_NODES];
__device__ __align__(16) float g_hs1   [(size_t)N_NODES * NH];  // (x@W1) * dinv[row]
__device__ __align__(16) float g_hs2   [(size_t)N_NODES * NC];  // dinv*(z@W2)

// ---------------- helpers ----------------
__device__ __forceinline__ unsigned int f2tf32(float f) {
    unsigned int r;
    asm("cvt.rna.tf32.f32 %0, %1;" : "=r"(r) : "f"(f));
    return r;
}
__device__ __forceinline__ void mma_tf32(float* c, const unsigned int* a, const unsigned int* b) {
    asm("mma.sync.aligned.m16n8k8.row.col.f32.tf32.tf32.f32 "
        "{%0,%1,%2,%3}, {%4,%5,%6,%7}, {%8,%9}, {%0,%1,%2,%3};"
        : "+f"(c[0]), "+f"(c[1]), "+f"(c[2]), "+f"(c[3])
        : "r"(a[0]), "r"(a[1]), "r"(a[2]), "r"(a[3]), "r"(b[0]), "r"(b[1]));
}

// ---------------- degree / dinv / CSR ----------------
__global__ void k_zero_cnt() {
    int i = blockIdx.x * blockDim.x + threadIdx.x;
    if (i < N_NODES) g_cnt[i] = 0;
}
__global__ void k_deg(const int* __restrict__ ei) {
    int e = blockIdx.x * blockDim.x + threadIdx.x;
    if (e < N_EDGES) atomicAdd(&g_cnt[ei[N_EDGES + e]], 1);
}
__global__ void k_dinv() {
    int i = blockIdx.x * blockDim.x + threadIdx.x;
    if (i < N_NODES) g_dinv[i] = rsqrtf((float)g_cnt[i] + 1.0f);  // +1 self loop
}

// ---- parallel scan, phase 1: per-128-chunk local exclusive scan + block sums ----
__global__ void __launch_bounds__(SCAN_CH) k_scan1() {
    __shared__ int wsum[4];
    const int t = threadIdx.x;
    const int i = blockIdx.x * SCAN_CH + t;
    const int lane = t & 31, warp = t >> 5;

    int v = (i < N_NODES) ? g_cnt[i] : 0;
    // warp inclusive scan
    int s = v;
    #pragma unroll
    for (int off = 1; off < 32; off <<= 1) {
        int u = __shfl_up_sync(0xffffffffu, s, off);
        if (lane >= off) s += u;
    }
    if (lane == 31) wsum[warp] = s;
    __syncthreads();
    int wo = 0;
    #pragma unroll
    for (int w = 0; w < 4; w++) if (w < warp) wo += wsum[w];
    if (i < N_NODES) g_rowptr[i] = wo + s - v;   // local exclusive prefix
    if (t == SCAN_CH - 1) g_bsum[blockIdx.x] = wo + s;
}
// ---- phase 2: single-block scan of 782 block sums (exclusive -> g_boff) ----
__global__ void __launch_bounds__(1024) k_scan2() {
    __shared__ int sh[1024];
    const int t = threadIdx.x;
    int v = (t < SCAN_NB) ? g_bsum[t] : 0;
    sh[t] = v;
    __syncthreads();
    #pragma unroll
    for (int off = 1; off < 1024; off <<= 1) {
        int add = (t >= off) ? sh[t - off] : 0;
        __syncthreads();
        sh[t] += add;
        __syncthreads();
    }
    if (t < SCAN_NB) g_boff[t] = sh[t] - v;      // exclusive
    if (t == 0) g_rowptr[N_NODES] = sh[1023];    // total (= N_EDGES)
}
// ---- phase 3: add block offsets; materialize cursor ----
__global__ void __launch_bounds__(SCAN_CH) k_scan3() {
    const int i = blockIdx.x * SCAN_CH + threadIdx.x;
    if (i < N_NODES) {
        int r = g_rowptr[i] + g_boff[blockIdx.x];
        g_rowptr[i] = r;
        g_cursor[i] = r;
    }
}
__global__ void k_fill(const int* __restrict__ ei) {
    int e = blockIdx.x * blockDim.x + threadIdx.x;
    if (e < N_EDGES) {
        int s = ei[e], d = ei[N_EDGES + e];
        int pos = atomicAdd(&g_cursor[d], 1);
        g_csr[pos] = s;
    }
}

// ---------------- GEMM1 (tf32 tensor cores): hs1 = (x@W1)*dinv ----------------
#define BM 128
#define BK 32
#define AS_STR 36
#define BS_STR 132
__global__ void __launch_bounds__(256, 2)
k_gemm1(const float* __restrict__ X, const float* __restrict__ W1) {
    __shared__ unsigned int As[BM][AS_STR];   // tf32 bits, [row][k]
    __shared__ unsigned int Bs[BK][BS_STR];   // tf32 bits, [k][col]

    const int tid    = threadIdx.x;
    const int lane   = tid & 31;
    const int wid    = tid >> 5;
    const int warp_m = wid >> 2;
    const int warp_n = wid & 3;
    const int block_row = blockIdx.x * BM;

    const int grp = lane >> 2;
    const int qid = lane & 3;

    float acc[4][4][4];
    #pragma unroll
    for (int i = 0; i < 4; i++)
        #pragma unroll
        for (int j = 0; j < 4; j++)
            #pragma unroll
            for (int q = 0; q < 4; q++) acc[i][j][q] = 0.0f;

    for (int k0 = 0; k0 < NF; k0 += BK) {
        #pragma unroll
        for (int i = 0; i < 4; i++) {
            int idx = tid + i * 256;
            int r   = idx >> 3;
            int c4  = (idx & 7) * 4;
            int grow = block_row + r;
            float4 v = make_float4(0.f, 0.f, 0.f, 0.f);
            if (grow < N_NODES)
                v = *(const float4*)(X + (size_t)grow * NF + k0 + c4);
            As[r][c4 + 0] = f2tf32(v.x);
            As[r][c4 + 1] = f2tf32(v.y);
            As[r][c4 + 2] = f2tf32(v.z);
            As[r][c4 + 3] = f2tf32(v.w);
        }
        #pragma unroll
        for (int i = 0; i < 4; i++) {
            int idx = tid + i * 256;
            int r   = idx >> 5;
            int c4  = (idx & 31) * 4;
            float4 v = *(const float4*)(W1 + (size_t)(k0 + r) * NH + c4);
            Bs[r][c4 + 0] = f2tf32(v.x);
            Bs[r][c4 + 1] = f2tf32(v.y);
            Bs[r][c4 + 2] = f2tf32(v.z);
            Bs[r][c4 + 3] = f2tf32(v.w);
        }
        __syncthreads();

        #pragma unroll
        for (int kk = 0; kk < BK; kk += 8) {
            unsigned int af[4][4];
            #pragma unroll
            for (int mt = 0; mt < 4; mt++) {
                int r = warp_m * 64 + mt * 16;
                af[mt][0] = As[r + grp    ][kk + qid    ];
                af[mt][1] = As[r + grp + 8][kk + qid    ];
                af[mt][2] = As[r + grp    ][kk + qid + 4];
                af[mt][3] = As[r + grp + 8][kk + qid + 4];
            }
            unsigned int bf[4][2];
            #pragma unroll
            for (int nt = 0; nt < 4; nt++) {
                int c = warp_n * 32 + nt * 8 + grp;
                bf[nt][0] = Bs[kk + qid    ][c];
                bf[nt][1] = Bs[kk + qid + 4][c];
            }
            #pragma unroll
            for (int mt = 0; mt < 4; mt++)
                #pragma unroll
                for (int nt = 0; nt < 4; nt++)
                    mma_tf32(acc[mt][nt], af[mt], bf[nt]);
        }
        __syncthreads();
    }

    #pragma unroll
    for (int mt = 0; mt < 4; mt++) {
        int r1 = block_row + warp_m * 64 + mt * 16 + grp;
        int r2 = r1 + 8;
        float dv1 = (r1 < N_NODES) ? g_dinv[r1] : 0.0f;
        float dv2 = (r2 < N_NODES) ? g_dinv[r2] : 0.0f;
        #pragma unroll
        for (int nt = 0; nt < 4; nt++) {
            int col = warp_n * 32 + nt * 8 + qid * 2;
            if (r1 < N_NODES)
                *(float2*)(g_hs1 + (size_t)r1 * NH + col) =
                    make_float2(acc[mt][nt][0] * dv1, acc[mt][nt][1] * dv1);
            if (r2 < N_NODES)
                *(float2*)(g_hs1 + (size_t)r2 * NH + col) =
                    make_float2(acc[mt][nt][2] * dv2, acc[mt][nt][3] * dv2);
        }
    }
}

// ---- layer1: per node, gather hs1 neighbors + self, relu(dinv*agg+b1), GEMV W2 ----
__global__ void __launch_bounds__(256)
k_layer1(const float* __restrict__ b1, const float* __restrict__ W2) {
    __shared__ float W2s[NH * NC];    // 20 KB  [k*NC+c]
    __shared__ float zs[8][NH];       // one z row per warp
    __shared__ float b1s[NH];

    const int tid  = threadIdx.x;
    const int warp = tid >> 5;
    const int lane = tid & 31;

    #pragma unroll
    for (int i = 0; i < 20; i++) {
        int idx = tid + i * 256;
        if (idx < NH * NC) W2s[idx] = W2[idx];
    }
    if (tid < NH) b1s[tid] = b1[tid];
    __syncthreads();

    #pragma unroll 1
    for (int it = 0; it < 4; it++) {
        int n = blockIdx.x * 32 + it * 8 + warp;
        float dv = g_dinv[n];

        float4 acc = *(const float4*)(g_hs1 + (size_t)n * NH + lane * 4);
        int beg = g_rowptr[n], end = g_rowptr[n + 1];
        int s_next = (beg < end) ? g_csr[beg] : 0;
        for (int e = beg; e < end; e++) {
            int s = s_next;
            if (e + 1 < end) s_next = g_csr[e + 1];
            float4 v = *(const float4*)(g_hs1 + (size_t)s * NH + lane * 4);
            acc.x += v.x; acc.y += v.y; acc.z += v.z; acc.w += v.w;
        }
        zs[warp][lane * 4 + 0] = fmaxf(dv * acc.x + b1s[lane * 4 + 0], 0.0f);
        zs[warp][lane * 4 + 1] = fmaxf(dv * acc.y + b1s[lane * 4 + 1], 0.0f);
        zs[warp][lane * 4 + 2] = fmaxf(dv * acc.z + b1s[lane * 4 + 2], 0.0f);
        zs[warp][lane * 4 + 3] = fmaxf(dv * acc.w + b1s[lane * 4 + 3], 0.0f);
        __syncwarp();

        float d0 = 0.0f, d1 = 0.0f;
        #pragma unroll 8
        for (int k = 0; k < NH; k++) {
            float zk = zs[warp][k];
            d0 = fmaf(zk, W2s[k * NC + lane], d0);
            if (lane < 8) d1 = fmaf(zk, W2s[k * NC + 32 + lane], d1);
        }
        g_hs2[(size_t)n * NC + lane] = dv * d0;
        if (lane < 8) g_hs2[(size_t)n * NC + 32 + lane] = dv * d1;
        __syncwarp();
    }
}

// ---- layer2: per node, gather hs2 neighbors + self, bias + log_softmax -> out ----
__global__ void __launch_bounds__(256)
k_layer2(const float* __restrict__ b2, float* __restrict__ out) {
    int n    = blockIdx.x * 8 + (threadIdx.x >> 5);
    int lane = threadIdx.x & 31;
    float dv = g_dinv[n];
    size_t base = (size_t)n * NC;

    float v0 = g_hs2[base + lane];
    float v1 = (lane < 8) ? g_hs2[base + 32 + lane] : 0.0f;

    int beg = g_rowptr[n], end = g_rowptr[n + 1];
    int s_next = (beg < end) ? g_csr[beg] : 0;
    for (int e = beg; e < end; e++) {
        int s = s_next;
        if (e + 1 < end) s_next = g_csr[e + 1];
        size_t sb = (size_t)s * NC;
        v0 += g_hs2[sb + lane];
        if (lane < 8) v1 += g_hs2[sb + 32 + lane];
    }

    v0 = dv * v0 + b2[lane];
    v1 = (lane < 8) ? (dv * v1 + b2[32 + lane]) : -3.0e38f;

    float m = fmaxf(v0, v1);
    #pragma unroll
    for (int off = 16; off; off >>= 1)
        m = fmaxf(m, __shfl_xor_sync(0xffffffffu, m, off));

    float ssum = expf(v0 - m) + ((lane < 8) ? expf(v1 - m) : 0.0f);
    #pragma unroll
    for (int off = 16; off; off >>= 1)
        ssum += __shfl_xor_sync(0xffffffffu, ssum, off);

    float lse = m + logf(ssum);
    out[base + lane] = v0 - lse;
    if (lane < 8) out[base + 32 + lane] = v1 - lse;
}

// ---------------- launch ----------------
extern "C" void kernel_launch(void* const* d_in, const int* in_sizes, int n_in,
                              void* d_out, int out_size) {
    const float* x = 0; const int* ei = 0;
    const float* W1 = 0; const float* b1 = 0;
    const float* W2 = 0; const float* b2 = 0;
    for (int i = 0; i < n_in; i++) {
        switch (in_sizes[i]) {
            case 51200000: x  = (const float*)d_in[i]; break;
            case 3200000:  ei = (const int*)d_in[i];   break;
            case 65536:    W1 = (const float*)d_in[i]; break;
            case 128:      b1 = (const float*)d_in[i]; break;
            case 5120:     W2 = (const float*)d_in[i]; break;
            case 40:       b2 = (const float*)d_in[i]; break;
        }
    }
    float* out = (float*)d_out;

    k_zero_cnt<<<(N_NODES + 255) / 256, 256>>>();
    k_deg<<<(N_EDGES + 255) / 256, 256>>>(ei);
    k_dinv<<<(N_NODES + 255) / 256, 256>>>();
    k_scan1<<<SCAN_NB, SCAN_CH>>>();
    k_scan2<<<1, 1024>>>();
    k_scan3<<<SCAN_NB, SCAN_CH>>>();
    k_fill<<<(N_EDGES + 255) / 256, 256>>>(ei);

    k_gemm1<<<(N_NODES + BM - 1) / BM, 256>>>(x, W1);   // 782 blocks, tf32 MMA
    k_layer1<<<N_NODES / 32, 256>>>(b1, W2);            // 3125 blocks
    k_layer2<<<N_NODES / 8, 256>>>(b2, out);            // 12500 blocks
}